// round 17
// baseline (speedup 1.0000x reference)
#include <cuda_runtime.h>

// ============================================================================
// 2-layer tanh RNN, B=32, L=2048, H=512 — v16: v12 structure (proven best)
// + pipelined flag polls + per-warp publication + fast tanh.
//
// 128 persistent CTAs (1/SM), 512 threads (16 warps):
//   CTA 0..63   : layer 0 (A), output cols [cta*8, cta*8+8)
//   CTA 64..127 : layer 1 (B), cols [(cta-64)*8, ...)
// Warps split by GEMM SIDE (v12):
//   A early (0..7):  x-side full-K (UNGATED) -> comb
//   A late  (8..15): gate AL&AH[t-1] (+B[t-8]) -> h-side full-K -> reduce
//                    -> +comb -> tanh -> publish ring
//   B early (0..7):  gate AL&AH[t] -> ring-side full-K -> comb
//   B late  (8..15): gate B[t-1] -> h1-side full-K -> reduce -> +comb
//                    -> tanh -> publish out
// Pair (wp, 8+wp) covers rows 4wp..4wp+3; combine via BAR64(3+wp) + comb
// double buffer (parity t&1). Leader-warp polls (w0/w8) + BAR256 release.
//
// v16 deltas (latency only, zero structural change):
//  - pipelined polls: 4-deep rotating in-flight acquire window -> flag
//    sample period ~RTT/4 instead of ~RTT (saves ~200 cyc/gate).
//  - per-warp publication: STG -> __syncwarp -> lane0 red.release.gpu.add
//    (final BAR256 convoy removed). Flag targets: AL/AH=256, B=512.
//  - tanh_fast: clamp +/-20, e=__expf(2x) (MUFU.EX2), (e-1)/(e+1) via
//    __fdividef (~60 cyc vs ~180; per-step err ~1e-6, budget 1e-3).
// Dataflow: L0 h -> 8-slot global ring; L1 h -> d_out. __ldcg cross-SM reads.
// fp32 packed fma.rn.f32x2 numerics otherwise identical.
// ============================================================================

#define BB 32
#define LL 2048
#define HH 512
#define GA 64
#define GB 64
#define NTHR 512

__device__ float g_ring[8 * BB * HH];   // layer-0 h ring, 8 slots, 512 KB
__device__ int   g_flagAL[LL];          // A cols [0,256)   done at t (tgt 256)
__device__ int   g_flagAH[LL];          // A cols [256,512) done at t (tgt 256)
__device__ int   g_flagB[LL];           // B done at t (tgt 512)

__device__ __forceinline__ int acq(const int* p) {
    int v;
    asm volatile("ld.acquire.gpu.global.b32 %0, [%1];" : "=r"(v) : "l"(p) : "memory");
    return v;
}
__device__ __forceinline__ void rel_add(int* p) {
    asm volatile("red.release.gpu.global.add.u32 [%0], %1;"
                 :: "l"(p), "r"(1u) : "memory");
}

// ---- pipelined polls: 4-deep rotating in-flight window, sample ~RTT/4 ----
__device__ __forceinline__ void wait1p(const int* p, int tp) {
    int a0 = acq(p), a1 = acq(p), a2 = acq(p), a3 = acq(p);
    while (true) {
        if (a0 >= tp) break;  a0 = acq(p);
        if (a1 >= tp) break;  a1 = acq(p);
        if (a2 >= tp) break;  a2 = acq(p);
        if (a3 >= tp) break;  a3 = acq(p);
    }
}
__device__ __forceinline__ void wait2p(const int* p, int tp,
                                       const int* q, int tq) {
    int a0 = acq(p), b0 = acq(q), a1 = acq(p), b1 = acq(q);
    while (true) {
        if (a0 >= tp && b0 >= tq) break;  a0 = acq(p); b0 = acq(q);
        if (a1 >= tp && b1 >= tq) break;  a1 = acq(p); b1 = acq(q);
    }
}
__device__ __forceinline__ void wait3p(const int* p, int tp,
                                       const int* q, int tq,
                                       const int* r, int tr) {
    int a0 = acq(p), b0 = acq(q), c0 = acq(r);
    int a1 = acq(p), b1 = acq(q), c1 = acq(r);
    while (true) {
        if (a0 >= tp && b0 >= tq && c0 >= tr) break;
        a0 = acq(p); b0 = acq(q); c0 = acq(r);
        if (a1 >= tp && b1 >= tq && c1 >= tr) break;
        a1 = acq(p); b1 = acq(q); c1 = acq(r);
    }
}

#define BAR256(id) asm volatile("bar.sync %0, 256;" :: "r"(id) : "memory")
#define BAR64(id)  asm volatile("bar.sync %0, 64;"  :: "r"(id) : "memory")

#define FMA2(d, a, w) asm volatile("fma.rn.f32x2 %0, %1, %2, %0;" \
                                   : "+l"(d) : "l"(a), "l"(w))

__device__ __forceinline__ unsigned long long pack2(float v) {
    unsigned long long r;
    asm("mov.b64 %0, {%1,%1};" : "=l"(r) : "f"(v));
    return r;
}

// Fast tanh: MUFU.EX2-based; rel err ~1e-6 per step (threshold 1e-3).
__device__ __forceinline__ float tanh_fast(float x) {
    float xc = fminf(fmaxf(x, -20.f), 20.f);
    float e  = __expf(2.f * xc);
    return __fdividef(e - 1.f, e + 1.f);
}

__global__ void zero_flags_kernel() {
    int i = blockIdx.x * blockDim.x + threadIdx.x;
    if (i < LL) { g_flagAL[i] = 0; g_flagAH[i] = 0; g_flagB[i] = 0; }
}

// Full-K accumulation of ONE side: all 16 LDG.128 batched up front (MLP=16).
// acc[b*4+q] packs cols (2q,2q+1) for row b0+b. Weights lane-interleaved:
// [(i4*4+e)*32+ln] = k = 128*i4 + 4*ln + e.
__device__ __forceinline__ void accum_both(
    unsigned long long acc[16],
    const ulonglong2* __restrict__ wA, const ulonglong2* __restrict__ wB,
    const float* __restrict__ p, long long stride, int b0, int ln, bool cg)
{
    float4 v[4][4];   // [i4][b]
    #pragma unroll
    for (int i4 = 0; i4 < 4; i4++)
        #pragma unroll
        for (int b = 0; b < 4; b++) {
            const float4* a = (const float4*)(p + (long long)(b0 + b) * stride
                                              + 128 * i4 + 4 * ln);
            v[i4][b] = cg ? __ldcg(a) : *a;
        }
    #pragma unroll
    for (int i4 = 0; i4 < 4; i4++)
        #pragma unroll
        for (int e = 0; e < 4; e++) {
            ulonglong2 a  = wA[(i4 * 4 + e) * 32 + ln];
            ulonglong2 bq = wB[(i4 * 4 + e) * 32 + ln];
            #pragma unroll
            for (int b = 0; b < 4; b++) {
                float xv = (e == 0) ? v[i4][b].x : (e == 1) ? v[i4][b].y
                         : (e == 2) ? v[i4][b].z : v[i4][b].w;
                unsigned long long xp = pack2(xv);
                FMA2(acc[b * 4 + 0], xp, a.x);
                FMA2(acc[b * 4 + 1], xp, a.y);
                FMA2(acc[b * 4 + 2], xp, bq.x);
                FMA2(acc[b * 4 + 3], xp, bq.y);
            }
        }
}

// Per-warp transpose-reduce over the 32-lane K split.
__device__ __forceinline__ float reduce32(const unsigned long long acc[16],
                                          float* redw, int ln)
{
    #pragma unroll
    for (int i = 0; i < 16; i++) {
        float2 v = *reinterpret_cast<const float2*>(&acc[i]);
        int a = (i >> 2) * 8 + (i & 3) * 2;
        redw[ln * 33 + a]     = v.x;
        redw[ln * 33 + a + 1] = v.y;
    }
    __syncwarp();
    float s0 = 0.f, s1 = 0.f, s2 = 0.f, s3 = 0.f;
    #pragma unroll
    for (int a = 0; a < 32; a += 4) {
        s0 += redw[(a + 0) * 33 + ln];
        s1 += redw[(a + 1) * 33 + ln];
        s2 += redw[(a + 2) * 33 + ln];
        s3 += redw[(a + 3) * 33 + ln];
    }
    __syncwarp();
    return (s0 + s1) + (s2 + s3);
}

__global__ __launch_bounds__(NTHR, 1) void rnn_kernel(
    const float* __restrict__ x,   const float* __restrict__ h0in,
    const float* __restrict__ Wi,  const float* __restrict__ bi,
    const float* __restrict__ Wh,  const float* __restrict__ bh,
    float* __restrict__ out, int write_final)
{
    extern __shared__ float smem[];
    ulonglong2* sWiA = (ulonglong2*)smem;      // [512] Wi cols 0-3
    ulonglong2* sWiB = sWiA + HH;              // [512] Wi cols 4-7
    ulonglong2* sWhA = sWiB + HH;              // [512] Wh cols 0-3
    ulonglong2* sWhB = sWhA + HH;              // [512] Wh cols 4-7
    float*      red  = (float*)(sWhB + HH);    // [16 warps][32][33]
    float*      comb = red + 16 * 32 * 33;     // [2][256] early->late combine

    const int  cta   = blockIdx.x;
    const bool isA   = (cta < GA);
    const int  layer = isA ? 0 : 1;
    const int  c0    = (isA ? cta : cta - GA) * 8;
    const int  tid   = threadIdx.x;
    const int  w     = tid >> 5;
    const int  ln    = tid & 31;
    const int  late  = w >> 3;          // 0 = early side, 1 = late (critical)
    const int  wp    = w & 7;           // pair index
    const int  b0    = 4 * wp;

    // ---- stage weight slices once ----
    {
        const float* wi_g = Wi + (size_t)layer * HH * HH + c0;
        const float* wh_g = Wh + (size_t)layer * HH * HH + c0;
        for (int k = tid; k < HH; k += NTHR) {
            int idx = ((k >> 7) * 4 + (k & 3)) * 32 + ((k >> 2) & 31);
            const ulonglong2* ri = (const ulonglong2*)(wi_g + (size_t)k * HH);
            const ulonglong2* rh = (const ulonglong2*)(wh_g + (size_t)k * HH);
            sWiA[idx] = ri[0];  sWiB[idx] = ri[1];
            sWhA[idx] = rh[0];  sWhB[idx] = rh[1];
        }
    }
    __syncthreads();    // one-time; no CTA-wide barrier in the loop

    const int   myb  = b0 + (ln >> 3);
    const int   myc  = c0 + (ln & 7);
    const float bias = bi[layer * HH + myc] + bh[layer * HH + myc];
    float* redw = red + w * (32 * 33);
    const int ci = wp * 32 + ln;

    if (isA) {
        if (!late) {
            // ===== A EARLY: x-side full-K, UNGATED =====
            #pragma unroll 1
            for (int t = 0; t < LL; t++) {
                unsigned long long acc[16];
                #pragma unroll
                for (int i = 0; i < 16; i++) acc[i] = 0ull;
                accum_both(acc, sWiA, sWiB, x + (long long)t * HH,
                           (long long)LL * HH, b0, ln, false);
                comb[(t & 1) * 256 + ci] = reduce32(acc, redw, ln);
                BAR64(3 + wp);
            }
        } else {
            // ===== A LATE: gate -> h-side full-K -> publish =====
            #pragma unroll 1
            for (int t = 0; t < LL; t++) {
                unsigned long long acc[16];
                #pragma unroll
                for (int i = 0; i < 16; i++) acc[i] = 0ull;
                if (t == 0) {
                    accum_both(acc, sWhA, sWhB, h0in, HH, b0, ln, false);
                } else {
                    if (w == 8) {
                        if (t >= 8)
                            wait3p(&g_flagAL[t-1], 256, &g_flagAH[t-1], 256,
                                   &g_flagB[t-8], 512);
                        else
                            wait2p(&g_flagAL[t-1], 256, &g_flagAH[t-1], 256);
                    }
                    BAR256(2);
                    accum_both(acc, sWhA, sWhB,
                               g_ring + ((t - 1) & 7) * (BB * HH),
                               HH, b0, ln, true);
                }
                float psum = reduce32(acc, redw, ln);
                BAR64(3 + wp);   // x-side partial ready in comb
                float hval = tanh_fast(psum + comb[(t & 1) * 256 + ci] + bias);
                g_ring[(t & 7) * (BB * HH) + myb * HH + myc] = hval;
                if (write_final && t == LL - 1)
                    out[(long long)BB * LL * HH + myb * HH + myc] = hval;
                __syncwarp();    // this warp's STGs issued
                if (ln == 0)
                    rel_add(cta < 32 ? &g_flagAL[t] : &g_flagAH[t]);
            }
        }
    } else {
        if (!late) {
            // ===== B EARLY: gate AL&AH[t] -> ring-side full-K =====
            #pragma unroll 1
            for (int t = 0; t < LL; t++) {
                unsigned long long acc[16];
                #pragma unroll
                for (int i = 0; i < 16; i++) acc[i] = 0ull;
                if (w == 0)
                    wait2p(&g_flagAL[t], 256, &g_flagAH[t], 256);
                BAR256(1);
                accum_both(acc, sWiA, sWiB, g_ring + (t & 7) * (BB * HH),
                           HH, b0, ln, true);
                comb[(t & 1) * 256 + ci] = reduce32(acc, redw, ln);
                BAR64(3 + wp);
            }
        } else {
            // ===== B LATE: gate B[t-1] -> h1-side full-K -> publish =====
            #pragma unroll 1
            for (int t = 0; t < LL; t++) {
                unsigned long long acc[16];
                #pragma unroll
                for (int i = 0; i < 16; i++) acc[i] = 0ull;
                if (t == 0) {
                    accum_both(acc, sWhA, sWhB, h0in + BB * HH,
                               HH, b0, ln, false);
                } else {
                    if (w == 8) wait1p(&g_flagB[t-1], 512);
                    BAR256(2);
                    accum_both(acc, sWhA, sWhB, out + (long long)(t - 1) * HH,
                               (long long)LL * HH, b0, ln, true);
                }
                float psum = reduce32(acc, redw, ln);
                BAR64(3 + wp);   // ring-side partial ready in comb
                float hval = tanh_fast(psum + comb[(t & 1) * 256 + ci] + bias);
                out[(long long)myb * LL * HH + (long long)t * HH + myc] = hval;
                if (write_final && t == LL - 1)
                    out[(long long)BB * LL * HH + BB * HH + myb * HH + myc] = hval;
                __syncwarp();    // this warp's STGs issued
                if (ln == 0) rel_add(&g_flagB[t]);
            }
        }
    }
}

extern "C" void kernel_launch(void* const* d_in, const int* in_sizes, int n_in,
                              void* d_out, int out_size)
{
    const float* x  = (const float*)d_in[0];
    const float* h0 = (const float*)d_in[1];
    const float* Wi = (const float*)d_in[2];
    const float* bi = (const float*)d_in[3];
    const float* Wh = (const float*)d_in[4];
    const float* bh = (const float*)d_in[5];
    float* out = (float*)d_out;

    int write_final = (out_size >= BB * LL * HH + 2 * BB * HH) ? 1 : 0;

    size_t smem = (size_t)(4 * HH * 16)                    // weights 32 KB
                + (size_t)(16 * 32 * 33) * sizeof(float)   // red    ~66 KB
                + (size_t)(2 * 256) * sizeof(float);       // comb     2 KB
    cudaFuncSetAttribute(rnn_kernel,
                         cudaFuncAttributeMaxDynamicSharedMemorySize, (int)smem);

    zero_flags_kernel<<<(LL + 255) / 256, 256>>>();
    rnn_kernel<<<GA + GB, NTHR, smem>>>(x, h0, Wi, bi, Wh, bh, out, write_final);
}